// round 4
// baseline (speedup 1.0000x reference)
#include <cuda_runtime.h>

// StateSpaceDiffusionModel: y[b,h,:] = causal_conv(u[b,h,:], f[h,:])
// reduced exactly to a scalar order-64 IIR+FIR (transposed direct form II):
//   y_t = c0*u_t + S[1]
//   S[i] <- S[i+1] + A'[i]*y_t + C'[i]*u_t   (merged delay line, i=1..64)
// A'[i] = a_{i-1} (1<=i<=64), C'[i] = c_i (1<=i<=63).
// a_j = w_j*P_j, c_i = k_i*P_i from the companion matrix M of the reference.
//
// Pair-state trick: each slot kept UNREDUCED as (sigma, tau), S = sigma+tau.
// 2-step update is then elementwise in f32x2 with PACKED data (y0,y1)/(u0,u1)
// and packed constants -- zero duplicate-broadcast MOVs in the hot loop.

#define HH 512
#define NN 64
#define BB 16
#define LL 2048

__device__ float g_a[HH * NN];
__device__ float g_c[HH * NN];

// ---------------- Kernel 1: per-head coefficients (trivial) ----------------
__global__ void coef_kernel(const float* __restrict__ k) {
    __shared__ float sh[NN];
    __shared__ float shd[NN];
    __shared__ float shP[NN];
    __shared__ float shsum;
    int h = blockIdx.x;
    int j = threadIdx.x;
    float kv = k[h * NN + j];
    float kc = fminf(fmaxf(kv, 1.0f / 16.0f), 1.0f);
    sh[j] = kc;
    __syncthreads();
    if (j == 0) {
        float s = 0.f;
        for (int i = 0; i < NN; i++) s += sh[i];
        shsum = s;
    }
    __syncthreads();
    float kn = kc / shsum;                       // L1-normalized clamped k
    float s = (j < NN - 1) ? (1.0f + kn) : kn;   // column L1 norm of (A + b k^T)
    float w = kn / s;                            // M[0, j]
    shd[j] = 1.0f / s;                           // M[j+1, j] subdiagonal
    __syncthreads();
    if (j == 0) {
        float P = 1.f;
        for (int i = 0; i < NN; i++) { shP[i] = P; P *= shd[i]; }
    }
    __syncthreads();
    float Pj = shP[j];
    g_a[h * NN + j] = w * Pj;    // IIR taps
    g_c[h * NN + j] = kv * Pj;   // FIR taps (original k!)
}

// ---------------- packed f32x2 helpers ----------------
typedef unsigned long long ull;
__device__ __forceinline__ ull pack2(float lo, float hi) {
    ull r; asm("mov.b64 %0, {%1,%2};" : "=l"(r) : "f"(lo), "f"(hi)); return r;
}
__device__ __forceinline__ void unpack2(ull v, float& lo, float& hi) {
    asm("mov.b64 {%0,%1}, %2;" : "=f"(lo), "=f"(hi) : "l"(v));
}
__device__ __forceinline__ ull fma2(ull a, ull b, ull c) {
    ull d; asm("fma.rn.f32x2 %0, %1, %2, %3;" : "=l"(d) : "l"(a), "l"(b), "l"(c)); return d;
}

// ---------------- Kernel 2: fused scan, pair-state, 8 lanes/seq ------------
// Warp = 4 sequences x 8 lanes; lane r owns slots 8r+1 .. 8r+8 (Spair[0..7]).
// Per 2-step iteration:
//   Spair''[i] = fma2(Cp[i], (u0,u1), fma2(Ap[i], (y0,y1), Spair[i+2]))
//   Ap[i] = (A'[s+1], A'[s]), Cp[i] = (C'[s+1], C'[s]),  s = 8r+1+i
// Boundary: slots 8r+9, 8r+10 come from next lane's Spair[0], Spair[1].
// u read as float4 (2 iterations per load) through a 4-slot register FIFO.
#define PD2 4   // float4 FIFO slots; each slot feeds 2 iterations (4 timesteps)

__global__ void __launch_bounds__(128, 4)
scan_kernel(const float* __restrict__ u, float* __restrict__ y) {
    int warp = blockIdx.x * (blockDim.x >> 5) + (threadIdx.x >> 5);
    int lane = threadIdx.x & 31;
    int g = lane >> 3;   // sequence within warp (0..3)
    int r = lane & 7;    // lane within group (0..7)
    int seq = warp * 4 + g;           // 0..8191
    int h = seq & (HH - 1);
    const float4* ubase4 = (const float4*)(u + (size_t)seq * LL);
    float* ybase = y + (size_t)seq * LL;

    const float* ah = g_a + h * NN;
    const float* ch = g_c + h * NN;

    ull Ap[8], Cp[8], S[8];
#pragma unroll
    for (int i = 0; i < 8; i++) {
        int s = 8 * r + 1 + i;  // slot index 1..64
        // A'[idx] = a[idx-1] for 1<=idx<=64 ; C'[idx] = c[idx] for 1<=idx<=63
        float Ahi = (s + 1 <= 64) ? ah[s] : 0.f;       // A'[s+1]
        float Alo = ah[s - 1];                          // A'[s] (s<=64 always)
        float Chi = (s + 1 <= 63) ? ch[s + 1] : 0.f;   // C'[s+1]
        float Clo = (s <= 63) ? ch[s] : 0.f;           // C'[s]
        Ap[i] = pack2(Ahi, Alo);
        Cp[i] = pack2(Chi, Clo);
        S[i] = 0ull;
    }
    float c0h = ch[0], c1h = ch[1], a0h = ah[0];

    // prologue: fill FIFO (each slot covers 4 timesteps)
    float4 buf[PD2];
#pragma unroll
    for (int j = 0; j < PD2; j++)
        buf[j] = ubase4[j];

    const int NQ = LL / 4;  // 512 four-step chunks
    for (int q0 = 0; q0 < NQ; q0 += PD2) {
#pragma unroll
        for (int j = 0; j < PD2; j++) {
            int q = q0 + j;             // chunk index: timesteps 4q..4q+3
            float4 cur = buf[j];
            int qp = q + PD2;
            if (qp > NQ - 1) qp = NQ - 1;   // clamped refill (unused if OOB)
            buf[j] = ubase4[qp];

#pragma unroll
            for (int half = 0; half < 2; half++) {
                float u0 = half ? cur.z : cur.x;
                float u1 = half ? cur.w : cur.y;

                // boundary: next lane's slots (old Spair[0], Spair[1]); r==7 -> 0
                ull bn0 = __shfl_down_sync(0xffffffffu, S[0], 1);
                ull bn1 = __shfl_down_sync(0xffffffffu, S[1], 1);
                if (r == 7) { bn0 = 0ull; bn1 = 0ull; }

                // leader computes y from OLD slots 1,2 (garbage off-leader)
                float s1a, s1b, s2a, s2b;
                unpack2(S[0], s1a, s1b);
                unpack2(S[1], s2a, s2b);
                float y0 = fmaf(c0h, u0, s1a + s1b);
                float y1 = fmaf(a0h, y0,
                            fmaf(c1h, u0, fmaf(c0h, u1, s2a + s2b)));
                // broadcast packed (y0,y1) from group leader
                ull ypk = __shfl_sync(0xffffffffu, pack2(y0, y1), 0, 8);
                ull upk = pack2(u0, u1);

#pragma unroll
                for (int i = 0; i < 6; i++)
                    S[i] = fma2(Cp[i], upk, fma2(Ap[i], ypk, S[i + 2]));
                S[6] = fma2(Cp[6], upk, fma2(Ap[6], ypk, bn0));
                S[7] = fma2(Cp[7], upk, fma2(Ap[7], ypk, bn1));

                if (r == 0)
                    *(ull*)(ybase + 4 * q + 2 * half) = ypk;  // (y0,y1)
            }
        }
    }
}

extern "C" void kernel_launch(void* const* d_in, const int* in_sizes, int n_in,
                              void* d_out, int out_size) {
    const float* u = (const float*)d_in[0];
    const float* k = (const float*)d_in[1];
    if (n_in >= 2 && in_sizes[0] == HH * NN) {  // defensive: swap if order differs
        u = (const float*)d_in[1];
        k = (const float*)d_in[0];
    }
    float* y = (float*)d_out;

    coef_kernel<<<HH, NN>>>(k);
    // 8192 sequences, 4 per warp, 4 warps per 128-thread CTA -> 512 CTAs
    scan_kernel<<<(BB * HH) / 16, 128>>>(u, y);
}

// round 5
// speedup vs baseline: 1.6980x; 1.6980x over previous
#include <cuda_runtime.h>

// StateSpaceDiffusionModel: y[b,h,:] = causal_conv(u[b,h,:], f[h,:])
// reduced exactly to a scalar order-64 IIR+FIR (transposed direct form II):
//   y_t = c0*u_t + S[1]
//   S[i] <- S[i+1] + A'[i]*y_t + C'[i]*u_t   (merged delay line, i=1..64)
// A'[i] = a_{i-1} (1<=i<=64), C'[i] = c_i (1<=i<=63).
// a_j = w_j*P_j, c_i = k_i*P_i from the companion matrix M of the reference.
//
// M=4 blocked form (this round): per iteration process 4 timesteps.
//   leader solves the 4x4 lower-triangular head for y0..y3, ONE broadcast,
//   then every slot takes 4 A-taps and 4 C-taps:
//   S''[s] = S_old[s+4] + sum_{m=0..3} A'(s+m)*y_{3-m} + C'(s+m)*u_{3-m}

#define HH 512
#define NN 64
#define BB 16
#define LL 2048

__device__ float g_a[HH * NN];
__device__ float g_c[HH * NN];

// ---------------- Kernel 1: per-head coefficients (trivial) ----------------
__global__ void coef_kernel(const float* __restrict__ k) {
    __shared__ float sh[NN];
    __shared__ float shd[NN];
    __shared__ float shP[NN];
    __shared__ float shsum;
    int h = blockIdx.x;
    int j = threadIdx.x;
    float kv = k[h * NN + j];
    float kc = fminf(fmaxf(kv, 1.0f / 16.0f), 1.0f);
    sh[j] = kc;
    __syncthreads();
    if (j == 0) {
        float s = 0.f;
        for (int i = 0; i < NN; i++) s += sh[i];
        shsum = s;
    }
    __syncthreads();
    float kn = kc / shsum;                       // L1-normalized clamped k
    float s = (j < NN - 1) ? (1.0f + kn) : kn;   // column L1 norm of (A + b k^T)
    float w = kn / s;                            // M[0, j]
    shd[j] = 1.0f / s;                           // M[j+1, j] subdiagonal
    __syncthreads();
    if (j == 0) {
        float P = 1.f;
        for (int i = 0; i < NN; i++) { shP[i] = P; P *= shd[i]; }
    }
    __syncthreads();
    float Pj = shP[j];
    g_a[h * NN + j] = w * Pj;    // IIR taps
    g_c[h * NN + j] = kv * Pj;   // FIR taps (original k!)
}

// ---------------- packed f32x2 helpers ----------------
typedef unsigned long long ull;
__device__ __forceinline__ ull pack2(float lo, float hi) {
    ull r; asm("mov.b64 %0, {%1,%2};" : "=l"(r) : "f"(lo), "f"(hi)); return r;
}
__device__ __forceinline__ void unpack2(ull v, float& lo, float& hi) {
    asm("mov.b64 {%0,%1}, %2;" : "=f"(lo), "=f"(hi) : "l"(v));
}
__device__ __forceinline__ ull fma2(ull a, ull b, ull c) {
    ull d; asm("fma.rn.f32x2 %0, %1, %2, %3;" : "=l"(d) : "l"(a), "l"(b), "l"(c)); return d;
}

// ---------------- Kernel 2: M=4 blocked scan, 8 lanes/seq ------------------
// Warp = 4 sequences x 8 lanes; lane r owns pairs (slots 8r+1..8r+8) as
// S[0..3], S[p] = (slot 8r+2p+1, slot 8r+2p+2) scalar values.
// Tap windows (pp = 0..4), base slot s = 8r+2pp+1:
//   Ao[pp] = (A'(s),   A'(s+1)),  Ae[pp] = (A'(s+1), A'(s+2))
//   Co[pp] = (C'(s),   C'(s+1)),  Ce[pp] = (C'(s+1), C'(s+2))
// Per 4-step iteration:
//   S''[p] = Ao[p]*y3d + Ae[p]*y2d + Ao[p+1]*y1d + Ae[p+1]*y0d
//          + Co[p]*u3d + Ce[p]*u2d + Co[p+1]*u1d + Ce[p+1]*u0d + S_old[p+2]
// Boundary: S_old[4],S_old[5] = next lane's old S[0],S[1] (zero on r==7).
#define PD 4   // float4 FIFO slots; each slot = one 4-step iteration

__global__ void __launch_bounds__(128, 4)
scan_kernel(const float* __restrict__ u, float* __restrict__ y) {
    int warp = blockIdx.x * (blockDim.x >> 5) + (threadIdx.x >> 5);
    int lane = threadIdx.x & 31;
    int g = lane >> 3;   // sequence within warp (0..3)
    int r = lane & 7;    // lane within group (0..7)
    int leader = lane & ~7;
    int seq = warp * 4 + g;           // 0..8191
    int h = seq & (HH - 1);
    const float4* ubase4 = (const float4*)(u + (size_t)seq * LL);
    float4* ybase4 = (float4*)(y + (size_t)seq * LL);

    const float* ah = g_a + h * NN;
    const float* ch = g_c + h * NN;

    // A'(i) = a[i-1] for 1<=i<=64 else 0 ; C'(i) = c[i] for 1<=i<=63 else 0
    ull Ao[5], Ae[5], Co[5], Ce[5], S[4];
#pragma unroll
    for (int pp = 0; pp < 5; pp++) {
        int s = 8 * r + 2 * pp + 1;  // base slot
        float A0v = (s     <= 64) ? ah[s - 1] : 0.f;
        float A1v = (s + 1 <= 64) ? ah[s]     : 0.f;
        float A2v = (s + 2 <= 64) ? ah[s + 1] : 0.f;
        float C0v = (s     <= 63) ? ch[s]     : 0.f;
        float C1v = (s + 1 <= 63) ? ch[s + 1] : 0.f;
        float C2v = (s + 2 <= 63) ? ch[s + 2] : 0.f;
        Ao[pp] = pack2(A0v, A1v);
        Ae[pp] = pack2(A1v, A2v);
        Co[pp] = pack2(C0v, C1v);
        Ce[pp] = pack2(C1v, C2v);
    }
#pragma unroll
    for (int p = 0; p < 4; p++) S[p] = 0ull;

    // solve coefficients (slots 1..3 taps + c0)
    float c0h = ch[0];
    float A1h = ah[0], A2h = ah[1], A3h = ah[2];
    float C1h = ch[1], C2h = ch[2], C3h = ch[3];

    // prologue: fill FIFO (each slot = 4 timesteps)
    float4 buf[PD];
#pragma unroll
    for (int j = 0; j < PD; j++)
        buf[j] = ubase4[j];

    const int NQ = LL / 4;  // 512 iterations
    for (int q0 = 0; q0 < NQ; q0 += PD) {
#pragma unroll
        for (int j = 0; j < PD; j++) {
            int q = q0 + j;
            float4 cur = buf[j];
            int qp = q + PD;
            if (qp > NQ - 1) qp = NQ - 1;   // clamped refill (unused if OOB)
            buf[j] = ubase4[qp];

            float u0 = cur.x, u1 = cur.y, u2 = cur.z, u3 = cur.w;

            // boundary: next lane's OLD S[0], S[1]; r==7 -> zero
            ull bn0 = __shfl_down_sync(0xffffffffu, S[0], 1);
            ull bn1 = __shfl_down_sync(0xffffffffu, S[1], 1);
            if (r == 7) { bn0 = 0ull; bn1 = 0ull; }

            // ---- 4-step triangular solve (meaningful on leader only) ----
            float t1, t2, t3, t4;
            unpack2(S[0], t1, t2);
            unpack2(S[1], t3, t4);
            // u-only parts first (off the y critical path)
            float p1 = fmaf(C1h, u0, fmaf(c0h, u1, t2));
            float p2 = fmaf(C2h, u0, fmaf(C1h, u1, fmaf(c0h, u2, t3)));
            float p3 = fmaf(C3h, u0, fmaf(C2h, u1, fmaf(C1h, u2, fmaf(c0h, u3, t4))));
            float y0 = fmaf(c0h, u0, t1);
            float y1 = fmaf(A1h, y0, p1);
            float y2 = fmaf(A1h, y1, fmaf(A2h, y0, p2));
            float y3 = fmaf(A1h, y2, fmaf(A2h, y1, fmaf(A3h, y0, p3)));

            // ---- single broadcast event: (y0,y1) and (y2,y3) ----
            ull ypk01 = __shfl_sync(0xffffffffu, pack2(y0, y1), leader);
            ull ypk23 = __shfl_sync(0xffffffffu, pack2(y2, y3), leader);
            float y0b, y1b, y2b, y3b;
            unpack2(ypk01, y0b, y1b);
            unpack2(ypk23, y2b, y3b);

            // duplicate-packed multiplicands (8 per 4 steps)
            ull y0d = pack2(y0b, y0b), y1d = pack2(y1b, y1b);
            ull y2d = pack2(y2b, y2b), y3d = pack2(y3b, y3b);
            ull u0d = pack2(u0, u0), u1d = pack2(u1, u1);
            ull u2d = pack2(u2, u2), u3d = pack2(u3, u3);

            // ---- slot updates: 8 fma2 per pair, independent chains ----
            ull n0 = fma2(Ao[0], y3d, fma2(Ae[0], y2d, fma2(Ao[1], y1d, fma2(Ae[1], y0d,
                     fma2(Co[0], u3d, fma2(Ce[0], u2d, fma2(Co[1], u1d, fma2(Ce[1], u0d, S[2]))))))));
            ull n1 = fma2(Ao[1], y3d, fma2(Ae[1], y2d, fma2(Ao[2], y1d, fma2(Ae[2], y0d,
                     fma2(Co[1], u3d, fma2(Ce[1], u2d, fma2(Co[2], u1d, fma2(Ce[2], u0d, S[3]))))))));
            ull n2 = fma2(Ao[2], y3d, fma2(Ae[2], y2d, fma2(Ao[3], y1d, fma2(Ae[3], y0d,
                     fma2(Co[2], u3d, fma2(Ce[2], u2d, fma2(Co[3], u1d, fma2(Ce[3], u0d, bn0))))))));
            ull n3 = fma2(Ao[3], y3d, fma2(Ae[3], y2d, fma2(Ao[4], y1d, fma2(Ae[4], y0d,
                     fma2(Co[3], u3d, fma2(Ce[3], u2d, fma2(Co[4], u1d, fma2(Ce[4], u0d, bn1))))))));
            S[0] = n0; S[1] = n1; S[2] = n2; S[3] = n3;

            if (r == 0)
                ybase4[q] = make_float4(y0b, y1b, y2b, y3b);
        }
    }
}

extern "C" void kernel_launch(void* const* d_in, const int* in_sizes, int n_in,
                              void* d_out, int out_size) {
    const float* u = (const float*)d_in[0];
    const float* k = (const float*)d_in[1];
    if (n_in >= 2 && in_sizes[0] == HH * NN) {  // defensive: swap if order differs
        u = (const float*)d_in[1];
        k = (const float*)d_in[0];
    }
    float* y = (float*)d_out;

    coef_kernel<<<HH, NN>>>(k);
    // 8192 sequences, 4 per warp, 4 warps per 128-thread CTA -> 512 CTAs
    scan_kernel<<<(BB * HH) / 16, 128>>>(u, y);
}